// round 5
// baseline (speedup 1.0000x reference)
#include <cuda_runtime.h>
#include <math.h>
#include <stdint.h>

#define SCALE 16
#define R_MAX 4
#define HL 32
#define WL 32
#define HH 512
#define WH 512
#define C_FEAT 128
#define HW (HH * WH)

// prep scratch
__device__ float g_guide_lr[3 * HL * WL];
__device__ float g_feat_t[HL * WL * C_FEAT];   // [spatial][channel]

// ---------------- dynamic smem layout (bytes) ----------------
// K padded to <=56; hi/lo interleaved -> row stride 114 floats (57 float2)
#define KSTRIDE_F  114
#define OFF_SCAL   0            // 8 floats
#define OFF_NACT   32           // int
#define OFF_SI     64           // int[64]
#define OFF_DXF    320          // float[64]
#define OFF_DYF    576          // float[64]
#define OFF_P0     832          // float4[64]
#define OFF_P1     1856         // float2[64]
#define OFF_DEN    2368         // float[512] (two partials per pixel)
#define OFF_W      4480         // 256 * 114 floats = 116736 B
#define OFF_F      (OFF_W + 256 * KSTRIDE_F * 4)     // 128 * 114 floats = 58368 B
#define SMEM_BYTES (OFF_F + 128 * KSTRIDE_F * 4)     // 179584 B
// staging buffer (epilogue) reuses OFF_W region: 128 ch * 260 floats = 133120 B
#define STAGE_STRIDE 260

static __device__ __forceinline__ uint32_t f2tf32(float f) {
    uint32_t r;
    asm("cvt.rna.tf32.f32 %0, %1;" : "=r"(r) : "f"(f));
    return r;
}

#define MMA_TF32(d, a0, a1, a2, a3, b0, b1) \
    asm volatile("mma.sync.aligned.m16n8k8.row.col.f32.tf32.tf32.f32 " \
        "{%0,%1,%2,%3}, {%4,%5,%6,%7}, {%8,%9}, {%0,%1,%2,%3};" \
        : "+f"((d)[0]), "+f"((d)[1]), "+f"((d)[2]), "+f"((d)[3]) \
        : "r"(a0), "r"(a1), "r"(a2), "r"(a3), "r"(b0), "r"(b1))

// ---------------------------------------------------------------------------
// Prep: transpose feat to channel-minor; bilinear-downsample guide (separable,
// rows then columns, matching the reference).
// ---------------------------------------------------------------------------
__global__ void jbu_prep_kernel(const float* __restrict__ feat,
                                const float* __restrict__ guide) {
    int idx = blockIdx.x * blockDim.x + threadIdx.x;

    if (idx < HL * WL * C_FEAT) {
        int c = idx & (C_FEAT - 1);
        int s = idx >> 7;
        g_feat_t[idx] = feat[c * (HL * WL) + s];
    }
    if (idx < 3 * HL * WL) {
        int c = idx >> 10;
        int rem = idx & 1023;
        int i = rem >> 5;
        int j = rem & 31;

        float srcy = fmaxf((i + 0.5f) * ((float)HH / HL) - 0.5f, 0.0f);
        int r0 = (int)floorf(srcy);
        float tr = srcy - (float)r0;
        int r0c = min(max(r0, 0), HH - 1);
        int r1c = min(max(r0 + 1, 0), HH - 1);

        float srcx = fmaxf((j + 0.5f) * ((float)WH / WL) - 0.5f, 0.0f);
        int c0 = (int)floorf(srcx);
        float tc = srcx - (float)c0;
        int c0c = min(max(c0, 0), WH - 1);
        int c1c = min(max(c0 + 1, 0), WH - 1);

        const float* g = guide + c * HW;
        float v0 = g[r0c * WH + c0c] * (1.0f - tr) + g[r1c * WH + c0c] * tr;
        float v1 = g[r0c * WH + c1c] * (1.0f - tr) + g[r1c * WH + c1c] * tr;
        g_guide_lr[idx] = v0 * (1.0f - tc) + v1 * tc;
    }
}

// ---------------------------------------------------------------------------
// Main: one block per LR cell. num = W[256xK] * F[Kx128] via mma.sync tf32
// (3xTF32 split). den exact fp32 (two thread-partials per pixel).
// Epilogue: scale in regs, stage in smem, coalesced float4 stores.
// ---------------------------------------------------------------------------
__global__ __launch_bounds__(512, 1)
void jbu_main_kernel(const float* __restrict__ guide,
                     const float* __restrict__ sx_raw,
                     const float* __restrict__ sy_raw,
                     const float* __restrict__ th_raw,
                     const float* __restrict__ sr_raw,
                     float* __restrict__ out) {
    extern __shared__ __align__(16) char smem[];

    float*  s_scal = (float*)(smem + OFF_SCAL);
    int*    s_nactp = (int*)(smem + OFF_NACT);
    int*    s_si   = (int*)(smem + OFF_SI);
    float*  s_dxf  = (float*)(smem + OFF_DXF);
    float*  s_dyf  = (float*)(smem + OFF_DYF);
    float4* s_p0   = (float4*)(smem + OFF_P0);
    float2* s_p1   = (float2*)(smem + OFF_P1);
    float*  s_den  = (float*)(smem + OFF_DEN);
    float*  Wf     = (float*)(smem + OFF_W);
    float*  Ff     = (float*)(smem + OFF_F);
    float*  stage  = (float*)(smem + OFF_W);   // reused after MMA

    const int uc = blockIdx.y;
    const int vc = blockIdx.x;
    const int tid = threadIdx.x;
    const int wid = tid >> 5;
    const int lane = tid & 31;

    // ---- phase 0: per-cell params + offset compaction ----
    if (tid == 0) {
        int cell = uc * WL + vc;
        float sx = fmaxf(expf(sx_raw[cell]), 1e-6f);
        float sy = fmaxf(expf(sy_raw[cell]), 1e-6f);
        float th = 3.14159265358979323846f * tanhf(th_raw[cell]);
        float sr = fmaxf(expf(sr_raw[cell]), 1e-6f);
        float rr = fminf(fmaxf(2.0f * fmaxf(sx, sy), 1.0f), (float)R_MAX);
        float Rsq = rr * rr;
        s_scal[0] = cosf(th);
        s_scal[1] = sinf(th);
        s_scal[2] = 1.0f / (2.0f * sx * sx + 1e-8f);
        s_scal[3] = 1.0f / (2.0f * sy * sy + 1e-8f);
        s_scal[4] = 1.0f / (2.0f * sr * sr + 1e-8f);
        int n = 0;
        for (int dy = -R_MAX; dy <= R_MAX; dy++) {
            for (int dx = -R_MAX; dx <= R_MAX; dx++) {
                if ((float)(dy * dy + dx * dx) <= Rsq) {
                    int ui = min(max(uc + dy, 0), HL - 1);
                    int vi = min(max(vc + dx, 0), WL - 1);
                    s_dyf[n] = (float)(uc - ui);
                    s_dxf[n] = (float)(vc - vi);
                    s_si[n]  = ui * WL + vi;
                    n++;
                }
            }
        }
        *s_nactp = n;   // <= 49
    }
    __syncthreads();

    const int nact = *s_nactp;
    const int kpad = (nact + 7) & ~7;
    const float ct  = s_scal[0];
    const float st  = s_scal[1];
    const float isx = s_scal[2];
    const float isy = s_scal[3];
    const float isr = s_scal[4];

    if (tid < nact) {
        int si = s_si[tid];
        float fdx = s_dxf[tid];
        float fdy = s_dyf[tid];
        float gl0 = g_guide_lr[si];
        float gl1 = g_guide_lr[HL * WL + si];
        float gl2 = g_guide_lr[2 * HL * WL + si];
        float A = fdx * ct + fdy * st;
        float B = fdy * ct - fdx * st;
        float D = (gl0 * gl0 + gl1 * gl1 + gl2 * gl2) * isr;
        s_p0[tid] = make_float4(A, B, D, 2.0f * gl0 * isr);
        s_p1[tid] = make_float2(2.0f * gl1 * isr, 2.0f * gl2 * isr);
    }
    __syncthreads();

    // ---- phase 1a: build W — ALL 512 threads, 2 threads per pixel ----
    {
        const int p  = tid & 255;
        const int kh = tid >> 8;           // 0/1: k parity
        const int ty = p >> 4, tx = p & 15;
        const int y = uc * SCALE + ty;
        const int x = vc * SCALE + tx;
        const float* gpix = guide + y * WH + x;
        const float g0 = gpix[0];
        const float g1 = gpix[HW];
        const float g2 = gpix[2 * HW];
        const float px = ((float)tx - 7.5f) * (1.0f / SCALE);
        const float py = ((float)ty - 7.5f) * (1.0f / SCALE);
        const float pa = px * ct + py * st;
        const float pb = py * ct - px * st;
        const float negE = -(g0 * g0 + g1 * g1 + g2 * g2) * isr;
        const float nisx = -isx, nisy = -isy;

        float den = 0.0f;
        float2* wrow = (float2*)(Wf + p * KSTRIDE_F);
        for (int k = kh; k < kpad; k += 2) {
            float w = 0.0f;
            if (k < nact) {
                float4 q0 = s_p0[k];
                float2 q1 = s_p1[k];
                float a = pa + q0.x;
                float b = pb + q0.y;
                float t = negE - q0.z;
                t = fmaf(g0, q0.w, t);
                t = fmaf(g1, q1.x, t);
                t = fmaf(g2, q1.y, t);
                t = fmaf(a * a, nisx, t);
                t = fmaf(b * b, nisy, t);
                w = __expf(t);
                den += w;
            }
            uint32_t h = f2tf32(w);
            uint32_t l = f2tf32(w - __uint_as_float(h));
            wrow[k] = make_float2(__uint_as_float(h), __uint_as_float(l));
        }
        s_den[kh * 256 + p] = den;
    }

    // ---- phase 1b: build F — ALL 512 threads, 4 threads per channel ----
    {
        const int c  = tid & 127;
        const int kq = tid >> 7;           // 0..3
        float2* frow = (float2*)(Ff + c * KSTRIDE_F);
        for (int k = kq; k < kpad; k += 4) {
            float f = (k < nact) ? g_feat_t[s_si[k] * C_FEAT + c] : 0.0f;
            uint32_t h = f2tf32(f);
            uint32_t l = f2tf32(f - __uint_as_float(h));
            frow[k] = make_float2(__uint_as_float(h), __uint_as_float(l));
        }
    }
    __syncthreads();

    // ---- phase 2: warp MMAs. warp = (pair, nhalf); 2 mtiles x 8 ntiles ----
    const int pair  = wid >> 1;       // 0..7  -> rows [pair*32, pair*32+32)
    const int nhalf = wid & 1;        // 0/1   -> cols [nhalf*64, +64)
    const int lq = lane >> 2;         // 0..7
    const int lr = lane & 3;          // 0..3

    float acc[2][8][4];
#pragma unroll
    for (int mt = 0; mt < 2; mt++)
#pragma unroll
        for (int nt = 0; nt < 8; nt++)
#pragma unroll
            for (int q = 0; q < 4; q++) acc[mt][nt][q] = 0.0f;

    const float2* W2 = (const float2*)Wf;
    const float2* F2 = (const float2*)Ff;
    const int rowb = pair * 32 + lq;
    const int nb   = nhalf * 64 + lq;
    const int ksteps = kpad >> 3;

    for (int ks = 0; ks < ksteps; ks++) {
        const int kq = ks * 8 + lr;
        uint32_t ah[2][4], al[2][4];
#pragma unroll
        for (int mt = 0; mt < 2; mt++) {
            int r0 = (rowb + mt * 16) * 57;
            float2 A0 = W2[r0 + kq];
            float2 A1 = W2[r0 + 8 * 57 + kq];
            float2 A2 = W2[r0 + kq + 4];
            float2 A3 = W2[r0 + 8 * 57 + kq + 4];
            ah[mt][0] = __float_as_uint(A0.x); al[mt][0] = __float_as_uint(A0.y);
            ah[mt][1] = __float_as_uint(A1.x); al[mt][1] = __float_as_uint(A1.y);
            ah[mt][2] = __float_as_uint(A2.x); al[mt][2] = __float_as_uint(A2.y);
            ah[mt][3] = __float_as_uint(A3.x); al[mt][3] = __float_as_uint(A3.y);
        }
#pragma unroll
        for (int nt = 0; nt < 8; nt++) {
            int nn = (nb + nt * 8) * 57;
            float2 B0 = F2[nn + kq];
            float2 B1 = F2[nn + kq + 4];
            uint32_t b0h = __float_as_uint(B0.x), b0l = __float_as_uint(B0.y);
            uint32_t b1h = __float_as_uint(B1.x), b1l = __float_as_uint(B1.y);
#pragma unroll
            for (int mt = 0; mt < 2; mt++) {
                MMA_TF32(acc[mt][nt], ah[mt][0], ah[mt][1], ah[mt][2], ah[mt][3], b0h, b1h);
                MMA_TF32(acc[mt][nt], al[mt][0], al[mt][1], al[mt][2], al[mt][3], b0h, b1h);
                MMA_TF32(acc[mt][nt], ah[mt][0], ah[mt][1], ah[mt][2], ah[mt][3], b0l, b1l);
            }
        }
    }

    // den per pixel (combine the 2 partials)
    float inv[2][2];
#pragma unroll
    for (int mt = 0; mt < 2; mt++) {
#pragma unroll
        for (int h = 0; h < 2; h++) {
            int p = pair * 32 + mt * 16 + h * 8 + lq;
            inv[mt][h] = 1.0f / fmaxf(s_den[p] + s_den[256 + p], 1e-8f);
        }
    }

    __syncthreads();   // everyone done reading W/F; stage buffer reuses that smem

    // ---- phase 3a: scale + stage to smem (conflict-free STS.32) ----
#pragma unroll
    for (int mt = 0; mt < 2; mt++) {
        const int px0 = pair * 32 + mt * 16 + lq;
#pragma unroll
        for (int nt = 0; nt < 8; nt++) {
            const int ch = nhalf * 64 + nt * 8 + lr * 2;
            stage[ch * STAGE_STRIDE + px0]           = acc[mt][nt][0] * inv[mt][0];
            stage[(ch + 1) * STAGE_STRIDE + px0]     = acc[mt][nt][1] * inv[mt][0];
            stage[ch * STAGE_STRIDE + px0 + 8]       = acc[mt][nt][2] * inv[mt][1];
            stage[(ch + 1) * STAGE_STRIDE + px0 + 8] = acc[mt][nt][3] * inv[mt][1];
        }
    }
    __syncthreads();

    // ---- phase 3b: coalesced stores. 8192 float4s, 16 per thread ----
    {
        float* obase = out + (size_t)(uc * SCALE) * WH + vc * SCALE;
#pragma unroll
        for (int i = 0; i < 16; i++) {
            int e4 = i * 512 + tid;
            int c   = e4 >> 6;           // 64 float4 per channel
            int rem = e4 & 63;
            int row = rem >> 2;
            int xq  = rem & 3;
            const float* sp = stage + c * STAGE_STRIDE + row * 16 + xq * 4;
            float4 v = *(const float4*)sp;
            *(float4*)(obase + (size_t)c * HW + (size_t)row * WH + xq * 4) = v;
        }
    }
}

extern "C" void kernel_launch(void* const* d_in, const int* in_sizes, int n_in,
                              void* d_out, int out_size) {
    const float* feat  = (const float*)d_in[0];
    const float* guide = (const float*)d_in[1];
    const float* sx    = (const float*)d_in[2];
    const float* sy    = (const float*)d_in[3];
    const float* th    = (const float*)d_in[4];
    const float* sr    = (const float*)d_in[5];
    float* out = (float*)d_out;

    cudaFuncSetAttribute(jbu_main_kernel,
                         cudaFuncAttributeMaxDynamicSharedMemorySize, SMEM_BYTES);

    jbu_prep_kernel<<<512, 256>>>(feat, guide);
    dim3 grid(WL, HL);
    jbu_main_kernel<<<grid, 512, SMEM_BYTES>>>(guide, sx, sy, th, sr, out);
}

// round 7
// speedup vs baseline: 1.5788x; 1.5788x over previous
#include <cuda_runtime.h>
#include <math.h>
#include <stdint.h>

#define SCALE 16
#define R_MAX 4
#define HL 32
#define WL 32
#define HH 512
#define WH 512
#define C_FEAT 128
#define HW (HH * WH)

// prep scratch
__device__ float g_guide_lr[3 * HL * WL];
__device__ float g_feat_t[HL * WL * C_FEAT];   // [spatial][channel]

// ---------------- dynamic smem layout (bytes) ----------------
// W/F stored as bf16x2 (one uint32 per kpair), hi and lo planes separate.
// Row stride 41 uint32: 41 mod 32 = 9, coprime -> STS conflict-free.
// All fragment loads are scalar 32-bit (4B alignment always valid).
#define KSLOT_STRIDE 41
#define OFF_SCAL   0            // 8 floats
#define OFF_NACT   32           // int
#define OFF_SI     64           // int[64]
#define OFF_DXF    320          // float[64]
#define OFF_DYF    576          // float[64]
#define OFF_P0     832          // float4[64]
#define OFF_P1     1856         // float2[64]
#define OFF_DEN    2368         // float[256]
#define OFF_WHI    4096
#define OFF_WLO    (OFF_WHI + 256 * KSLOT_STRIDE * 4)
#define OFF_FHI    (OFF_WLO + 256 * KSLOT_STRIDE * 4)
#define OFF_FLO    (OFF_FHI + 128 * KSLOT_STRIDE * 4)
#define SMEM_BYTES (OFF_FLO + 128 * KSLOT_STRIDE * 4)   // ~130 KB

// pack two floats to bf16x2 (lo 16 bits = w0)
static __device__ __forceinline__ uint32_t pack_bf16x2(float w0, float w1) {
    uint32_t r;
    asm("cvt.rn.bf16x2.f32 %0, %1, %2;" : "=r"(r) : "f"(w1), "f"(w0));
    return r;
}

#define MMA_BF16(d, a0, a1, a2, a3, b0, b1) \
    asm volatile("mma.sync.aligned.m16n8k16.row.col.f32.bf16.bf16.f32 " \
        "{%0,%1,%2,%3}, {%4,%5,%6,%7}, {%8,%9}, {%0,%1,%2,%3};" \
        : "+f"((d)[0]), "+f"((d)[1]), "+f"((d)[2]), "+f"((d)[3]) \
        : "r"(a0), "r"(a1), "r"(a2), "r"(a3), "r"(b0), "r"(b1))

// slot s (within a row) -> kpair index. ks = s>>3; within: j=(s&7)>>1, half=s&1.
// kp = ks*8 + j + 4*half  => thread lr reads slots {2lr, 2lr+1} = kpairs {lr, lr+4},
// exactly the m16n8k16 fragment k-ownership.
static __device__ __forceinline__ int slot_to_kpair(int s) {
    return ((s >> 3) << 3) + ((s & 7) >> 1) + ((s & 1) << 2);
}

// ---------------------------------------------------------------------------
// Prep: transpose feat to channel-minor; bilinear-downsample guide (separable,
// rows then columns, matching the reference).
// ---------------------------------------------------------------------------
__global__ void jbu_prep_kernel(const float* __restrict__ feat,
                                const float* __restrict__ guide) {
    int idx = blockIdx.x * blockDim.x + threadIdx.x;

    if (idx < HL * WL * C_FEAT) {
        int c = idx & (C_FEAT - 1);
        int s = idx >> 7;
        g_feat_t[idx] = feat[c * (HL * WL) + s];
    }
    if (idx < 3 * HL * WL) {
        int c = idx >> 10;
        int rem = idx & 1023;
        int i = rem >> 5;
        int j = rem & 31;

        float srcy = fmaxf((i + 0.5f) * ((float)HH / HL) - 0.5f, 0.0f);
        int r0 = (int)floorf(srcy);
        float tr = srcy - (float)r0;
        int r0c = min(max(r0, 0), HH - 1);
        int r1c = min(max(r0 + 1, 0), HH - 1);

        float srcx = fmaxf((j + 0.5f) * ((float)WH / WL) - 0.5f, 0.0f);
        int c0 = (int)floorf(srcx);
        float tc = srcx - (float)c0;
        int c0c = min(max(c0, 0), WH - 1);
        int c1c = min(max(c0 + 1, 0), WH - 1);

        const float* g = guide + c * HW;
        float v0 = g[r0c * WH + c0c] * (1.0f - tr) + g[r1c * WH + c0c] * tr;
        float v1 = g[r0c * WH + c1c] * (1.0f - tr) + g[r1c * WH + c1c] * tr;
        g_guide_lr[idx] = v0 * (1.0f - tc) + v1 * tc;
    }
}

// ---------------------------------------------------------------------------
// Main: one block per LR cell. num = W[256xK] * F[Kx128] via mma.sync bf16
// m16n8k16 with hi/lo split (hh + lh + hl). den exact fp32 during W build.
// ---------------------------------------------------------------------------
__global__ __launch_bounds__(512, 1)
void jbu_main_kernel(const float* __restrict__ guide,
                     const float* __restrict__ sx_raw,
                     const float* __restrict__ sy_raw,
                     const float* __restrict__ th_raw,
                     const float* __restrict__ sr_raw,
                     float* __restrict__ out) {
    extern __shared__ __align__(16) char smem[];

    float*    s_scal = (float*)(smem + OFF_SCAL);
    int*      s_nactp = (int*)(smem + OFF_NACT);
    int*      s_si   = (int*)(smem + OFF_SI);
    float*    s_dxf  = (float*)(smem + OFF_DXF);
    float*    s_dyf  = (float*)(smem + OFF_DYF);
    float4*   s_p0   = (float4*)(smem + OFF_P0);
    float2*   s_p1   = (float2*)(smem + OFF_P1);
    float*    s_den  = (float*)(smem + OFF_DEN);
    uint32_t* Whi    = (uint32_t*)(smem + OFF_WHI);
    uint32_t* Wlo    = (uint32_t*)(smem + OFF_WLO);
    uint32_t* Fhi    = (uint32_t*)(smem + OFF_FHI);
    uint32_t* Flo    = (uint32_t*)(smem + OFF_FLO);

    const int uc = blockIdx.y;
    const int vc = blockIdx.x;
    const int tid = threadIdx.x;
    const int wid = tid >> 5;
    const int lane = tid & 31;

    // ---- phase 0: per-cell params + offset compaction ----
    if (tid == 0) {
        int cell = uc * WL + vc;
        float sx = fmaxf(expf(sx_raw[cell]), 1e-6f);
        float sy = fmaxf(expf(sy_raw[cell]), 1e-6f);
        float th = 3.14159265358979323846f * tanhf(th_raw[cell]);
        float sr = fmaxf(expf(sr_raw[cell]), 1e-6f);
        float rr = fminf(fmaxf(2.0f * fmaxf(sx, sy), 1.0f), (float)R_MAX);
        float Rsq = rr * rr;
        s_scal[0] = cosf(th);
        s_scal[1] = sinf(th);
        s_scal[2] = 1.0f / (2.0f * sx * sx + 1e-8f);
        s_scal[3] = 1.0f / (2.0f * sy * sy + 1e-8f);
        s_scal[4] = 1.0f / (2.0f * sr * sr + 1e-8f);
        int n = 0;
        for (int dy = -R_MAX; dy <= R_MAX; dy++) {
            for (int dx = -R_MAX; dx <= R_MAX; dx++) {
                if ((float)(dy * dy + dx * dx) <= Rsq) {
                    int ui = min(max(uc + dy, 0), HL - 1);
                    int vi = min(max(vc + dx, 0), WL - 1);
                    s_dyf[n] = (float)(uc - ui);
                    s_dxf[n] = (float)(vc - vi);
                    s_si[n]  = ui * WL + vi;
                    n++;
                }
            }
        }
        *s_nactp = n;   // <= 49
    }
    __syncthreads();

    const int nact = *s_nactp;
    const int ksteps = (nact + 15) >> 4;   // m16n8k16 steps (<= 4)
    const int nslots = ksteps * 8;         // uint32 slots per row
    const float ct  = s_scal[0];
    const float st  = s_scal[1];
    const float isx = s_scal[2];
    const float isy = s_scal[3];
    const float isr = s_scal[4];

    if (tid < nact) {
        int si = s_si[tid];
        float fdx = s_dxf[tid];
        float fdy = s_dyf[tid];
        float gl0 = g_guide_lr[si];
        float gl1 = g_guide_lr[HL * WL + si];
        float gl2 = g_guide_lr[2 * HL * WL + si];
        float A = fdx * ct + fdy * st;
        float B = fdy * ct - fdx * st;
        float D = (gl0 * gl0 + gl1 * gl1 + gl2 * gl2) * isr;
        s_p0[tid] = make_float4(A, B, D, 2.0f * gl0 * isr);
        s_p1[tid] = make_float2(2.0f * gl1 * isr, 2.0f * gl2 * isr);
    }
    __syncthreads();

    // ---- phase 1: build W (threads 0-255) / F (threads 256-511), in parallel ----
    if (tid < 256) {
        const int p = tid;
        const int ty = p >> 4, tx = p & 15;
        const int y = uc * SCALE + ty;
        const int x = vc * SCALE + tx;
        const float* gpix = guide + y * WH + x;
        const float g0 = gpix[0];
        const float g1 = gpix[HW];
        const float g2 = gpix[2 * HW];
        const float px = ((float)tx - 7.5f) * (1.0f / SCALE);
        const float py = ((float)ty - 7.5f) * (1.0f / SCALE);
        const float pa = px * ct + py * st;
        const float pb = py * ct - px * st;
        const float negE = -(g0 * g0 + g1 * g1 + g2 * g2) * isr;
        const float nisx = -isx, nisy = -isy;

        float den = 0.0f;
        uint32_t* whrow = Whi + p * KSLOT_STRIDE;
        uint32_t* wlrow = Wlo + p * KSLOT_STRIDE;
        for (int s = 0; s < nslots; s++) {
            int kp = slot_to_kpair(s);
            float wv[2];
#pragma unroll
            for (int h = 0; h < 2; h++) {
                int k = 2 * kp + h;
                float w = 0.0f;
                if (k < nact) {
                    float4 q0 = s_p0[k];
                    float2 q1 = s_p1[k];
                    float a = pa + q0.x;
                    float b = pb + q0.y;
                    float t = negE - q0.z;
                    t = fmaf(g0, q0.w, t);
                    t = fmaf(g1, q1.x, t);
                    t = fmaf(g2, q1.y, t);
                    t = fmaf(a * a, nisx, t);
                    t = fmaf(b * b, nisy, t);
                    w = __expf(t);
                    den += w;
                }
                wv[h] = w;
            }
            uint32_t hi = pack_bf16x2(wv[0], wv[1]);
            float h0f = __uint_as_float(hi << 16);
            float h1f = __uint_as_float(hi & 0xffff0000u);
            uint32_t lo = pack_bf16x2(wv[0] - h0f, wv[1] - h1f);
            whrow[s] = hi;
            wlrow[s] = lo;
        }
        s_den[p] = den;
    } else {
        const int t = tid - 256;
        const int c  = t & 127;
        const int sq = t >> 7;           // 0/1: slot parity
        uint32_t* fhrow = Fhi + c * KSLOT_STRIDE;
        uint32_t* flrow = Flo + c * KSLOT_STRIDE;
        for (int s = sq; s < nslots; s += 2) {
            int kp = slot_to_kpair(s);
            int k0 = 2 * kp, k1 = 2 * kp + 1;
            float f0 = (k0 < nact) ? g_feat_t[s_si[k0] * C_FEAT + c] : 0.0f;
            float f1 = (k1 < nact) ? g_feat_t[s_si[k1] * C_FEAT + c] : 0.0f;
            uint32_t hi = pack_bf16x2(f0, f1);
            float h0f = __uint_as_float(hi << 16);
            float h1f = __uint_as_float(hi & 0xffff0000u);
            uint32_t lo = pack_bf16x2(f0 - h0f, f1 - h1f);
            fhrow[s] = hi;
            flrow[s] = lo;
        }
    }
    __syncthreads();

    // ---- phase 2: warp MMAs. warp = (pair, nhalf); 2 mtiles x 8 ntiles ----
    const int pair  = wid >> 1;       // 0..7  -> rows [pair*32, pair*32+32)
    const int nhalf = wid & 1;        // 0/1   -> cols [nhalf*64, +64)
    const int lq = lane >> 2;         // 0..7  (groupID)
    const int lr = lane & 3;          // 0..3  (threadID-in-group)

    float acc[2][8][4];
#pragma unroll
    for (int mt = 0; mt < 2; mt++)
#pragma unroll
        for (int nt = 0; nt < 8; nt++)
#pragma unroll
            for (int q = 0; q < 4; q++) acc[mt][nt][q] = 0.0f;

    const int rowb = pair * 32 + lq;
    const int slot0 = 2 * lr;

    for (int ks = 0; ks < ksteps; ks++) {
        const int sbase = ks * 8 + slot0;
        // A fragments: scalar 32-bit loads (4B alignment always valid)
        uint32_t ah0[2], ah1[2], ah2[2], ah3[2];
        uint32_t al0[2], al1[2], al2[2], al3[2];
#pragma unroll
        for (int mt = 0; mt < 2; mt++) {
            int r0 = (rowb + mt * 16) * KSLOT_STRIDE + sbase;
            int r1 = (rowb + mt * 16 + 8) * KSLOT_STRIDE + sbase;
            ah0[mt] = Whi[r0];     // row lq,   kpair lr
            ah1[mt] = Whi[r1];     // row lq+8, kpair lr
            ah2[mt] = Whi[r0 + 1]; // row lq,   kpair lr+4
            ah3[mt] = Whi[r1 + 1]; // row lq+8, kpair lr+4
            al0[mt] = Wlo[r0];
            al1[mt] = Wlo[r1];
            al2[mt] = Wlo[r0 + 1];
            al3[mt] = Wlo[r1 + 1];
        }
#pragma unroll
        for (int nt = 0; nt < 8; nt++) {
            const int ch = nhalf * 64 + nt * 8 + lq;
            const int fo = ch * KSLOT_STRIDE + sbase;
            uint32_t bh0 = Fhi[fo];
            uint32_t bh1 = Fhi[fo + 1];
            uint32_t bl0 = Flo[fo];
            uint32_t bl1 = Flo[fo + 1];
#pragma unroll
            for (int mt = 0; mt < 2; mt++) {
                MMA_BF16(acc[mt][nt], ah0[mt], ah1[mt], ah2[mt], ah3[mt], bh0, bh1);
                MMA_BF16(acc[mt][nt], al0[mt], al1[mt], al2[mt], al3[mt], bh0, bh1);
                MMA_BF16(acc[mt][nt], ah0[mt], ah1[mt], ah2[mt], ah3[mt], bl0, bl1);
            }
        }
    }

    // ---- phase 3: epilogue (direct stores, R4 layout) ----
    float invd[4];
#pragma unroll
    for (int q = 0; q < 4; q++)
        invd[q] = 1.0f / fmaxf(s_den[pair * 32 + q * 8 + lq], 1e-8f);

#pragma unroll
    for (int mt = 0; mt < 2; mt++) {
        const int p0 = pair * 32 + mt * 16 + lq;
        const int y = uc * SCALE + (p0 >> 4);
        const int x = vc * SCALE + (p0 & 15);
        const size_t off = (size_t)y * WH + x;
        const float i0 = invd[mt * 2];
        const float i1 = invd[mt * 2 + 1];
#pragma unroll
        for (int nt = 0; nt < 8; nt++) {
            const int ch = nhalf * 64 + nt * 8 + lr * 2;
            float* o = out + (size_t)ch * HW + off;
            o[0]      = acc[mt][nt][0] * i0;
            o[HW]     = acc[mt][nt][1] * i0;
            o[8]      = acc[mt][nt][2] * i1;
            o[HW + 8] = acc[mt][nt][3] * i1;
        }
    }
}

extern "C" void kernel_launch(void* const* d_in, const int* in_sizes, int n_in,
                              void* d_out, int out_size) {
    const float* feat  = (const float*)d_in[0];
    const float* guide = (const float*)d_in[1];
    const float* sx    = (const float*)d_in[2];
    const float* sy    = (const float*)d_in[3];
    const float* th    = (const float*)d_in[4];
    const float* sr    = (const float*)d_in[5];
    float* out = (float*)d_out;

    cudaFuncSetAttribute(jbu_main_kernel,
                         cudaFuncAttributeMaxDynamicSharedMemorySize, SMEM_BYTES);

    jbu_prep_kernel<<<512, 256>>>(feat, guide);
    dim3 grid(WL, HL);
    jbu_main_kernel<<<grid, 512, SMEM_BYTES>>>(guide, sx, sy, th, sr, out);
}

// round 8
// speedup vs baseline: 1.6500x; 1.0451x over previous
#include <cuda_runtime.h>
#include <math.h>
#include <stdint.h>

#define SCALE 16
#define R_MAX 4
#define HL 32
#define WL 32
#define HH 512
#define WH 512
#define C_FEAT 128
#define HW (HH * WH)

// prep scratch
__device__ float g_guide_lr[3 * HL * WL];
__device__ float g_feat_t[HL * WL * C_FEAT];   // [spatial][channel]

// ---------------- dynamic smem layout (bytes) ----------------
// Slot-major W/F: array[slot][item], stride 136 words (136 mod 32 = 8).
// Fragment loads: bank = 8*lr + lq  -> bijection, conflict-free.
// Build stores: consecutive lanes -> consecutive items -> conflict-free.
#define SLOT_STRIDE 136
#define NSLOT_MAX   32
#define OFF_SCAL   0            // floats: ct, st, isx, isy, isr, Rsq
#define OFF_NACT   32
#define OFF_SI     64           // int[64]
#define OFF_DXF    320          // float[64]
#define OFF_DYF    576          // float[64]
#define OFF_P0     832          // float4[64]
#define OFF_P1     1856         // float2[64]
#define OFF_DEN    2368         // float[256] (2 partials x 128 pixels)
#define OFF_WHI    3584
#define OFF_WLO    (OFF_WHI + NSLOT_MAX * SLOT_STRIDE * 4)   // +17408
#define OFF_FHI    (OFF_WLO + NSLOT_MAX * SLOT_STRIDE * 4)
#define OFF_FLO    (OFF_FHI + NSLOT_MAX * SLOT_STRIDE * 4)
#define SMEM_BYTES (OFF_FLO + NSLOT_MAX * SLOT_STRIDE * 4)   // 73216 B

// pack two floats to bf16x2 (lo 16 bits = w0)
static __device__ __forceinline__ uint32_t pack_bf16x2(float w0, float w1) {
    uint32_t r;
    asm("cvt.rn.bf16x2.f32 %0, %1, %2;" : "=r"(r) : "f"(w1), "f"(w0));
    return r;
}

#define MMA_BF16(d, a0, a1, a2, a3, b0, b1) \
    asm volatile("mma.sync.aligned.m16n8k16.row.col.f32.bf16.bf16.f32 " \
        "{%0,%1,%2,%3}, {%4,%5,%6,%7}, {%8,%9}, {%0,%1,%2,%3};" \
        : "+f"((d)[0]), "+f"((d)[1]), "+f"((d)[2]), "+f"((d)[3]) \
        : "r"(a0), "r"(a1), "r"(a2), "r"(a3), "r"(b0), "r"(b1))

// ---------------------------------------------------------------------------
// Prep: transpose feat to channel-minor; bilinear-downsample guide (separable,
// rows then columns, matching the reference).
// ---------------------------------------------------------------------------
__global__ void jbu_prep_kernel(const float* __restrict__ feat,
                                const float* __restrict__ guide) {
    int idx = blockIdx.x * blockDim.x + threadIdx.x;

    if (idx < HL * WL * C_FEAT) {
        int c = idx & (C_FEAT - 1);
        int s = idx >> 7;
        g_feat_t[idx] = feat[c * (HL * WL) + s];
    }
    if (idx < 3 * HL * WL) {
        int c = idx >> 10;
        int rem = idx & 1023;
        int i = rem >> 5;
        int j = rem & 31;

        float srcy = fmaxf((i + 0.5f) * ((float)HH / HL) - 0.5f, 0.0f);
        int r0 = (int)floorf(srcy);
        float tr = srcy - (float)r0;
        int r0c = min(max(r0, 0), HH - 1);
        int r1c = min(max(r0 + 1, 0), HH - 1);

        float srcx = fmaxf((j + 0.5f) * ((float)WH / WL) - 0.5f, 0.0f);
        int c0 = (int)floorf(srcx);
        float tc = srcx - (float)c0;
        int c0c = min(max(c0, 0), WH - 1);
        int c1c = min(max(c0 + 1, 0), WH - 1);

        const float* g = guide + c * HW;
        float v0 = g[r0c * WH + c0c] * (1.0f - tr) + g[r1c * WH + c0c] * tr;
        float v1 = g[r0c * WH + c1c] * (1.0f - tr) + g[r1c * WH + c1c] * tr;
        g_guide_lr[idx] = v0 * (1.0f - tc) + v1 * tc;
    }
}

// ---------------------------------------------------------------------------
// Main: one block per HALF LR cell (8 HR rows x 16 cols x 128 ch).
// num = W[128xK] * F[Kx128] via mma.sync bf16 m16n8k16, hi/lo split
// (hh + lh + hl). den exact fp32 (2 k-parity partials per pixel).
// 256 threads, 8 warps; warp w owns HR row w (m16: pixels x=0..15).
// ---------------------------------------------------------------------------
__global__ __launch_bounds__(256, 2)
void jbu_main_kernel(const float* __restrict__ guide,
                     const float* __restrict__ sx_raw,
                     const float* __restrict__ sy_raw,
                     const float* __restrict__ th_raw,
                     const float* __restrict__ sr_raw,
                     float* __restrict__ out) {
    extern __shared__ __align__(16) char smem[];

    float*    s_scal = (float*)(smem + OFF_SCAL);
    int*      s_nactp = (int*)(smem + OFF_NACT);
    int*      s_si   = (int*)(smem + OFF_SI);
    float*    s_dxf  = (float*)(smem + OFF_DXF);
    float*    s_dyf  = (float*)(smem + OFF_DYF);
    float4*   s_p0   = (float4*)(smem + OFF_P0);
    float2*   s_p1   = (float2*)(smem + OFF_P1);
    float*    s_den  = (float*)(smem + OFF_DEN);
    uint32_t* Whi    = (uint32_t*)(smem + OFF_WHI);
    uint32_t* Wlo    = (uint32_t*)(smem + OFF_WLO);
    uint32_t* Fhi    = (uint32_t*)(smem + OFF_FHI);
    uint32_t* Flo    = (uint32_t*)(smem + OFF_FLO);

    const int uc = blockIdx.y;
    const int vc = blockIdx.x;
    const int zh = blockIdx.z;       // 0/1: which 8-row half of the 16x16 tile
    const int tid = threadIdx.x;
    const int wid = tid >> 5;
    const int lane = tid & 31;

    // ---- phase 0: params + offset compaction (warp 0, ballot-based) ----
    if (wid == 0) {
        if (lane == 0) {
            int cell = uc * WL + vc;
            float sx = fmaxf(expf(sx_raw[cell]), 1e-6f);
            float sy = fmaxf(expf(sy_raw[cell]), 1e-6f);
            float th = 3.14159265358979323846f * tanhf(th_raw[cell]);
            float sr = fmaxf(expf(sr_raw[cell]), 1e-6f);
            float rr = fminf(fmaxf(2.0f * fmaxf(sx, sy), 1.0f), (float)R_MAX);
            s_scal[0] = cosf(th);
            s_scal[1] = sinf(th);
            s_scal[2] = 1.0f / (2.0f * sx * sx + 1e-8f);
            s_scal[3] = 1.0f / (2.0f * sy * sy + 1e-8f);
            s_scal[4] = 1.0f / (2.0f * sr * sr + 1e-8f);
            s_scal[5] = rr * rr;
        }
        __syncwarp();
        const float Rsq = s_scal[5];
        int base = 0;
#pragma unroll
        for (int chnk = 0; chnk < 3; chnk++) {
            int i = chnk * 32 + lane;
            int dy = i / 9 - R_MAX;
            int dx = i - (i / 9) * 9 - R_MAX;
            bool act = (i < 81) && ((float)(dy * dy + dx * dx) <= Rsq);
            unsigned m = __ballot_sync(0xffffffffu, act);
            int pos = base + __popc(m & ((1u << lane) - 1u));
            if (act) {
                int ui = min(max(uc + dy, 0), HL - 1);
                int vi = min(max(vc + dx, 0), WL - 1);
                s_dyf[pos] = (float)(uc - ui);
                s_dxf[pos] = (float)(vc - vi);
                s_si[pos]  = ui * WL + vi;
            }
            base += __popc(m);
        }
        if (lane == 0) *s_nactp = base;
    }
    __syncthreads();

    const int nact = *s_nactp;                 // <= 49
    const int ksteps = (nact + 15) >> 4;       // <= 4
    const int nslots = ksteps * 8;             // kpair slots, <= 32
    const float ct  = s_scal[0];
    const float st  = s_scal[1];
    const float isx = s_scal[2];
    const float isy = s_scal[3];
    const float isr = s_scal[4];

    if (tid < nact) {
        int si = s_si[tid];
        float fdx = s_dxf[tid];
        float fdy = s_dyf[tid];
        float gl0 = g_guide_lr[si];
        float gl1 = g_guide_lr[HL * WL + si];
        float gl2 = g_guide_lr[2 * HL * WL + si];
        float A = fdx * ct + fdy * st;
        float B = fdy * ct - fdx * st;
        float D = (gl0 * gl0 + gl1 * gl1 + gl2 * gl2) * isr;
        s_p0[tid] = make_float4(A, B, D, 2.0f * gl0 * isr);
        s_p1[tid] = make_float2(2.0f * gl1 * isr, 2.0f * gl2 * isr);
    }
    __syncthreads();

    // ---- phase 1a: build F (all 256 threads; slot-major, coalesced) ----
    {
        const int nent = nslots * C_FEAT;
        for (int e = tid; e < nent; e += 256) {
            int c = e & 127;
            int s = e >> 7;
            int k0 = 2 * s, k1 = 2 * s + 1;
            float f0 = (k0 < nact) ? g_feat_t[s_si[k0] * C_FEAT + c] : 0.0f;
            float f1 = (k1 < nact) ? g_feat_t[s_si[k1] * C_FEAT + c] : 0.0f;
            uint32_t hi = pack_bf16x2(f0, f1);
            float h0f = __uint_as_float(hi << 16);
            float h1f = __uint_as_float(hi & 0xffff0000u);
            uint32_t lo = pack_bf16x2(f0 - h0f, f1 - h1f);
            Fhi[s * SLOT_STRIDE + c] = hi;
            Flo[s * SLOT_STRIDE + c] = lo;
        }
    }

    // ---- phase 1b: build W (2 threads per pixel, k-parity split) ----
    {
        const int p  = tid & 127;          // pixel in this half (8 rows x 16)
        const int kh = tid >> 7;           // 0/1: slot parity
        const int r  = p >> 4;             // row within half
        const int tx = p & 15;
        const int tyc = zh * 8 + r;        // row within 16x16 cell
        const int y = uc * SCALE + tyc;
        const int x = vc * SCALE + tx;
        const float* gpix = guide + y * WH + x;
        const float g0 = gpix[0];
        const float g1 = gpix[HW];
        const float g2 = gpix[2 * HW];
        const float px = ((float)tx - 7.5f) * (1.0f / SCALE);
        const float py = ((float)tyc - 7.5f) * (1.0f / SCALE);
        const float pa = px * ct + py * st;
        const float pb = py * ct - px * st;
        const float negE = -(g0 * g0 + g1 * g1 + g2 * g2) * isr;
        const float nisx = -isx, nisy = -isy;

        float den = 0.0f;
        for (int s = kh; s < nslots; s += 2) {
            float wv[2];
#pragma unroll
            for (int h = 0; h < 2; h++) {
                int k = 2 * s + h;
                float w = 0.0f;
                if (k < nact) {
                    float4 q0 = s_p0[k];
                    float2 q1 = s_p1[k];
                    float a = pa + q0.x;
                    float b = pb + q0.y;
                    float t = negE - q0.z;
                    t = fmaf(g0, q0.w, t);
                    t = fmaf(g1, q1.x, t);
                    t = fmaf(g2, q1.y, t);
                    t = fmaf(a * a, nisx, t);
                    t = fmaf(b * b, nisy, t);
                    w = __expf(t);
                    den += w;
                }
                wv[h] = w;
            }
            uint32_t hi = pack_bf16x2(wv[0], wv[1]);
            float h0f = __uint_as_float(hi << 16);
            float h1f = __uint_as_float(hi & 0xffff0000u);
            uint32_t lo = pack_bf16x2(wv[0] - h0f, wv[1] - h1f);
            Whi[s * SLOT_STRIDE + p] = hi;
            Wlo[s * SLOT_STRIDE + p] = lo;
        }
        s_den[kh * 128 + p] = den;
    }
    __syncthreads();

    // ---- phase 2: warp MMAs. warp w owns HR row w: m16 x n128 ----
    const int lq = lane >> 2;         // 0..7  (groupID)
    const int lr = lane & 3;          // 0..3  (threadID-in-group)

    float acc[16][4];
#pragma unroll
    for (int nt = 0; nt < 16; nt++)
#pragma unroll
        for (int q = 0; q < 4; q++) acc[nt][q] = 0.0f;

    const int rowb = wid * 16 + lq;   // pixel row-base for A fragments

    for (int ks = 0; ks < ksteps; ks++) {
        const int sA = (ks * 8 + lr) * SLOT_STRIDE;        // kpair lr
        const int sB = (ks * 8 + lr + 4) * SLOT_STRIDE;    // kpair lr+4
        uint32_t ah0 = Whi[sA + rowb];
        uint32_t ah1 = Whi[sA + rowb + 8];
        uint32_t ah2 = Whi[sB + rowb];
        uint32_t ah3 = Whi[sB + rowb + 8];
        uint32_t al0 = Wlo[sA + rowb];
        uint32_t al1 = Wlo[sA + rowb + 8];
        uint32_t al2 = Wlo[sB + rowb];
        uint32_t al3 = Wlo[sB + rowb + 8];
#pragma unroll
        for (int nt = 0; nt < 16; nt++) {
            const int cb = nt * 8 + lq;
            uint32_t bh0 = Fhi[sA + cb];
            uint32_t bh1 = Fhi[sB + cb];
            uint32_t bl0 = Flo[sA + cb];
            uint32_t bl1 = Flo[sB + cb];
            MMA_BF16(acc[nt], ah0, ah1, ah2, ah3, bh0, bh1);
            MMA_BF16(acc[nt], al0, al1, al2, al3, bh0, bh1);
            MMA_BF16(acc[nt], ah0, ah1, ah2, ah3, bl0, bl1);
        }
    }

    // ---- phase 3: epilogue ----
    const int p0 = wid * 16 + lq;          // pixel: row wid, x = lq
    const int p1 = p0 + 8;                 //        row wid, x = lq+8
    const float inv0 = 1.0f / fmaxf(s_den[p0] + s_den[128 + p0], 1e-8f);
    const float inv1 = 1.0f / fmaxf(s_den[p1] + s_den[128 + p1], 1e-8f);
    const int y = uc * SCALE + zh * 8 + wid;
    const int xg = vc * SCALE + lq;
    float* obase = out + (size_t)y * WH + xg;

#pragma unroll
    for (int nt = 0; nt < 16; nt++) {
        const int ch = nt * 8 + lr * 2;
        float* o = obase + (size_t)ch * HW;
        o[0]      = acc[nt][0] * inv0;
        o[HW]     = acc[nt][1] * inv0;
        o[8]      = acc[nt][2] * inv1;
        o[HW + 8] = acc[nt][3] * inv1;
    }
}

extern "C" void kernel_launch(void* const* d_in, const int* in_sizes, int n_in,
                              void* d_out, int out_size) {
    const float* feat  = (const float*)d_in[0];
    const float* guide = (const float*)d_in[1];
    const float* sx    = (const float*)d_in[2];
    const float* sy    = (const float*)d_in[3];
    const float* th    = (const float*)d_in[4];
    const float* sr    = (const float*)d_in[5];
    float* out = (float*)d_out;

    cudaFuncSetAttribute(jbu_main_kernel,
                         cudaFuncAttributeMaxDynamicSharedMemorySize, SMEM_BYTES);

    jbu_prep_kernel<<<512, 256>>>(feat, guide);
    dim3 grid(WL, HL, 2);
    jbu_main_kernel<<<grid, 256, SMEM_BYTES>>>(guide, sx, sy, th, sr, out);
}

// round 9
// speedup vs baseline: 1.8347x; 1.1119x over previous
#include <cuda_runtime.h>
#include <math.h>
#include <stdint.h>

#define SCALE 16
#define R_MAX 4
#define HL 32
#define WL 32
#define HH 512
#define WH 512
#define C_FEAT 128
#define HW (HH * WH)

// prep scratch
__device__ float g_guide_lr[3 * HL * WL];
__device__ float g_feat_t[HL * WL * C_FEAT];   // [spatial][channel]

// ---------------- dynamic smem layout (bytes) ----------------
// F slot-major: array[slot][channel], stride 136 words (136 mod 32 = 8).
// Fragment loads: bank = 8*lr + lq -> bijection, conflict-free.
#define SLOT_STRIDE 136
#define NSLOT_MAX   32
#define OFF_SCAL   0            // floats: ct, st, isx, isy, isr, Rsq
#define OFF_NACT   32
#define OFF_SI     64           // int[64]
#define OFF_DXF    320          // float[64]
#define OFF_DYF    576          // float[64]
#define OFF_P0     832          // float4[64]
#define OFF_P1     1856         // float2[64]
#define OFF_FHI    2432
#define OFF_FLO    (OFF_FHI + NSLOT_MAX * SLOT_STRIDE * 4)
#define SMEM_BYTES (OFF_FLO + NSLOT_MAX * SLOT_STRIDE * 4)   // 37248 B

// pack two floats to bf16x2 (lo 16 bits = w0)
static __device__ __forceinline__ uint32_t pack_bf16x2(float w0, float w1) {
    uint32_t r;
    asm("cvt.rn.bf16x2.f32 %0, %1, %2;" : "=r"(r) : "f"(w1), "f"(w0));
    return r;
}

#define MMA_BF16(d, a0, a1, a2, a3, b0, b1) \
    asm volatile("mma.sync.aligned.m16n8k16.row.col.f32.bf16.bf16.f32 " \
        "{%0,%1,%2,%3}, {%4,%5,%6,%7}, {%8,%9}, {%0,%1,%2,%3};" \
        : "+f"((d)[0]), "+f"((d)[1]), "+f"((d)[2]), "+f"((d)[3]) \
        : "r"(a0), "r"(a1), "r"(a2), "r"(a3), "r"(b0), "r"(b1))

// ---------------------------------------------------------------------------
// Prep: transpose feat to channel-minor; bilinear-downsample guide (separable,
// rows then columns, matching the reference).
// ---------------------------------------------------------------------------
__global__ void jbu_prep_kernel(const float* __restrict__ feat,
                                const float* __restrict__ guide) {
    int idx = blockIdx.x * blockDim.x + threadIdx.x;

    if (idx < HL * WL * C_FEAT) {
        int c = idx & (C_FEAT - 1);
        int s = idx >> 7;
        g_feat_t[idx] = feat[c * (HL * WL) + s];
    }
    if (idx < 3 * HL * WL) {
        int c = idx >> 10;
        int rem = idx & 1023;
        int i = rem >> 5;
        int j = rem & 31;

        float srcy = fmaxf((i + 0.5f) * ((float)HH / HL) - 0.5f, 0.0f);
        int r0 = (int)floorf(srcy);
        float tr = srcy - (float)r0;
        int r0c = min(max(r0, 0), HH - 1);
        int r1c = min(max(r0 + 1, 0), HH - 1);

        float srcx = fmaxf((j + 0.5f) * ((float)WH / WL) - 0.5f, 0.0f);
        int c0 = (int)floorf(srcx);
        float tc = srcx - (float)c0;
        int c0c = min(max(c0, 0), WH - 1);
        int c1c = min(max(c0 + 1, 0), WH - 1);

        const float* g = guide + c * HW;
        float v0 = g[r0c * WH + c0c] * (1.0f - tr) + g[r1c * WH + c0c] * tr;
        float v1 = g[r0c * WH + c1c] * (1.0f - tr) + g[r1c * WH + c1c] * tr;
        g_guide_lr[idx] = v0 * (1.0f - tc) + v1 * tc;
    }
}

// ---------------------------------------------------------------------------
// Main: one block per HALF LR cell (8 HR rows x 16 cols x 128 ch).
// num = W[128xK] * F[Kx128] via mma.sync bf16 m16n8k16, hi/lo split
// (hh + lh + hl). W (A fragments) computed IN REGISTERS by the owning thread,
// interleaved with the MMAs; only F is staged in smem. den exact fp32 via
// quad shfl reduction. 256 threads, 8 warps; warp w owns HR row w.
// ---------------------------------------------------------------------------
__global__ __launch_bounds__(256, 2)
void jbu_main_kernel(const float* __restrict__ guide,
                     const float* __restrict__ sx_raw,
                     const float* __restrict__ sy_raw,
                     const float* __restrict__ th_raw,
                     const float* __restrict__ sr_raw,
                     float* __restrict__ out) {
    extern __shared__ __align__(16) char smem[];

    float*    s_scal = (float*)(smem + OFF_SCAL);
    int*      s_nactp = (int*)(smem + OFF_NACT);
    int*      s_si   = (int*)(smem + OFF_SI);
    float*    s_dxf  = (float*)(smem + OFF_DXF);
    float*    s_dyf  = (float*)(smem + OFF_DYF);
    float4*   s_p0   = (float4*)(smem + OFF_P0);
    float2*   s_p1   = (float2*)(smem + OFF_P1);
    uint32_t* Fhi    = (uint32_t*)(smem + OFF_FHI);
    uint32_t* Flo    = (uint32_t*)(smem + OFF_FLO);

    const int uc = blockIdx.y;
    const int vc = blockIdx.x;
    const int zh = blockIdx.z;       // 0/1: which 8-row half of the 16x16 tile
    const int tid = threadIdx.x;
    const int wid = tid >> 5;
    const int lane = tid & 31;

    // ---- phase 0: params + offset compaction (warp 0, ballot-based) ----
    if (wid == 0) {
        if (lane == 0) {
            int cell = uc * WL + vc;
            float sx = fmaxf(expf(sx_raw[cell]), 1e-6f);
            float sy = fmaxf(expf(sy_raw[cell]), 1e-6f);
            float th = 3.14159265358979323846f * tanhf(th_raw[cell]);
            float sr = fmaxf(expf(sr_raw[cell]), 1e-6f);
            float rr = fminf(fmaxf(2.0f * fmaxf(sx, sy), 1.0f), (float)R_MAX);
            s_scal[0] = cosf(th);
            s_scal[1] = sinf(th);
            s_scal[2] = 1.0f / (2.0f * sx * sx + 1e-8f);
            s_scal[3] = 1.0f / (2.0f * sy * sy + 1e-8f);
            s_scal[4] = 1.0f / (2.0f * sr * sr + 1e-8f);
            s_scal[5] = rr * rr;
        }
        __syncwarp();
        const float Rsq = s_scal[5];
        int base = 0;
#pragma unroll
        for (int chnk = 0; chnk < 3; chnk++) {
            int i = chnk * 32 + lane;
            int dy = i / 9 - R_MAX;
            int dx = i - (i / 9) * 9 - R_MAX;
            bool act = (i < 81) && ((float)(dy * dy + dx * dx) <= Rsq);
            unsigned m = __ballot_sync(0xffffffffu, act);
            int pos = base + __popc(m & ((1u << lane) - 1u));
            if (act) {
                int ui = min(max(uc + dy, 0), HL - 1);
                int vi = min(max(vc + dx, 0), WL - 1);
                s_dyf[pos] = (float)(uc - ui);
                s_dxf[pos] = (float)(vc - vi);
                s_si[pos]  = ui * WL + vi;
            }
            base += __popc(m);
        }
        if (lane == 0) *s_nactp = base;
    }
    __syncthreads();

    const int nact = *s_nactp;                 // <= 49
    const int ksteps = (nact + 15) >> 4;       // <= 4
    const int nslots = ksteps * 8;             // kpair slots, <= 32
    const float ct  = s_scal[0];
    const float st  = s_scal[1];
    const float isx = s_scal[2];
    const float isy = s_scal[3];
    const float isr = s_scal[4];

    if (tid < nact) {
        int si = s_si[tid];
        float fdx = s_dxf[tid];
        float fdy = s_dyf[tid];
        float gl0 = g_guide_lr[si];
        float gl1 = g_guide_lr[HL * WL + si];
        float gl2 = g_guide_lr[2 * HL * WL + si];
        float A = fdx * ct + fdy * st;
        float B = fdy * ct - fdx * st;
        float D = (gl0 * gl0 + gl1 * gl1 + gl2 * gl2) * isr;
        s_p0[tid] = make_float4(A, B, D, 2.0f * gl0 * isr);
        s_p1[tid] = make_float2(2.0f * gl1 * isr, 2.0f * gl2 * isr);
    }
    __syncthreads();

    // ---- phase 1: build F (all 256 threads; slot-major, coalesced) ----
    {
        const int nent = nslots * C_FEAT;
        for (int e = tid; e < nent; e += 256) {
            int c = e & 127;
            int s = e >> 7;
            int k0 = 2 * s, k1 = 2 * s + 1;
            float f0 = (k0 < nact) ? g_feat_t[s_si[k0] * C_FEAT + c] : 0.0f;
            float f1 = (k1 < nact) ? g_feat_t[s_si[k1] * C_FEAT + c] : 0.0f;
            uint32_t hi = pack_bf16x2(f0, f1);
            float h0f = __uint_as_float(hi << 16);
            float h1f = __uint_as_float(hi & 0xffff0000u);
            uint32_t lo = pack_bf16x2(f0 - h0f, f1 - h1f);
            Fhi[s * SLOT_STRIDE + c] = hi;
            Flo[s * SLOT_STRIDE + c] = lo;
        }
    }

    // ---- per-pixel constants for the two pixels this thread owns ----
    const int lq = lane >> 2;         // 0..7  (groupID)
    const int lr = lane & 3;          // 0..3  (threadID-in-group)
    const int tyc = zh * 8 + wid;     // row within 16x16 cell
    const int y = uc * SCALE + tyc;
    const int x0 = vc * SCALE + lq;   // pixel 0: x=lq; pixel 1: x=lq+8

    const float* gp0 = guide + (size_t)y * WH + x0;
    const float ga0 = gp0[0],     ga1 = gp0[HW],     ga2 = gp0[2 * HW];
    const float gb0 = gp0[8],     gb1 = gp0[HW + 8], gb2 = gp0[2 * HW + 8];

    const float py = ((float)tyc - 7.5f) * (1.0f / SCALE);
    const float px0 = ((float)lq - 7.5f) * (1.0f / SCALE);
    const float px1 = ((float)(lq + 8) - 7.5f) * (1.0f / SCALE);
    const float pa0 = px0 * ct + py * st;
    const float pb0 = py * ct - px0 * st;
    const float pa1 = px1 * ct + py * st;
    const float pb1 = py * ct - px1 * st;
    const float negE0 = -(ga0 * ga0 + ga1 * ga1 + ga2 * ga2) * isr;
    const float negE1 = -(gb0 * gb0 + gb1 * gb1 + gb2 * gb2) * isr;
    const float nisx = -isx, nisy = -isy;

    float acc[16][4];
#pragma unroll
    for (int nt = 0; nt < 16; nt++)
#pragma unroll
        for (int q = 0; q < 4; q++) acc[nt][q] = 0.0f;
    float den0 = 0.0f, den1 = 0.0f;

    __syncthreads();   // F ready

    // ---- phase 2: fused W-eval + MMA ----
    for (int ks = 0; ks < ksteps; ks++) {
        // Evaluate 8 weights: jp = (pairsel<<1)|khalf gives k; both pixels per k.
        float w[4][2];
#pragma unroll
        for (int jp = 0; jp < 4; jp++) {
            int k = 2 * (ks * 8 + lr + ((jp >> 1) << 2)) + (jp & 1);
            float v0 = 0.0f, v1 = 0.0f;
            if (k < nact) {
                float4 q0 = s_p0[k];
                float2 q1 = s_p1[k];
                float a0 = pa0 + q0.x, b0 = pb0 + q0.y;
                float t0 = negE0 - q0.z;
                t0 = fmaf(ga0, q0.w, t0);
                t0 = fmaf(ga1, q1.x, t0);
                t0 = fmaf(ga2, q1.y, t0);
                t0 = fmaf(a0 * a0, nisx, t0);
                t0 = fmaf(b0 * b0, nisy, t0);
                v0 = __expf(t0);
                float a1 = pa1 + q0.x, b1 = pb1 + q0.y;
                float t1 = negE1 - q0.z;
                t1 = fmaf(gb0, q0.w, t1);
                t1 = fmaf(gb1, q1.x, t1);
                t1 = fmaf(gb2, q1.y, t1);
                t1 = fmaf(a1 * a1, nisx, t1);
                t1 = fmaf(b1 * b1, nisy, t1);
                v1 = __expf(t1);
            }
            w[jp][0] = v0;
            w[jp][1] = v1;
        }
        den0 += w[0][0] + w[1][0] + w[2][0] + w[3][0];
        den1 += w[0][1] + w[1][1] + w[2][1] + w[3][1];

        // A fragments (hi + residual-lo), k-order lo-bits-first
        uint32_t ah0 = pack_bf16x2(w[0][0], w[1][0]);
        uint32_t ah1 = pack_bf16x2(w[0][1], w[1][1]);
        uint32_t ah2 = pack_bf16x2(w[2][0], w[3][0]);
        uint32_t ah3 = pack_bf16x2(w[2][1], w[3][1]);
        uint32_t al0 = pack_bf16x2(w[0][0] - __uint_as_float(ah0 << 16),
                                   w[1][0] - __uint_as_float(ah0 & 0xffff0000u));
        uint32_t al1 = pack_bf16x2(w[0][1] - __uint_as_float(ah1 << 16),
                                   w[1][1] - __uint_as_float(ah1 & 0xffff0000u));
        uint32_t al2 = pack_bf16x2(w[2][0] - __uint_as_float(ah2 << 16),
                                   w[3][0] - __uint_as_float(ah2 & 0xffff0000u));
        uint32_t al3 = pack_bf16x2(w[2][1] - __uint_as_float(ah3 << 16),
                                   w[3][1] - __uint_as_float(ah3 & 0xffff0000u));

        const int sA = (ks * 8 + lr) * SLOT_STRIDE;        // kpair lr
        const int sB = (ks * 8 + lr + 4) * SLOT_STRIDE;    // kpair lr+4
#pragma unroll
        for (int nt = 0; nt < 16; nt++) {
            const int cb = nt * 8 + lq;
            uint32_t bh0 = Fhi[sA + cb];
            uint32_t bh1 = Fhi[sB + cb];
            uint32_t bl0 = Flo[sA + cb];
            uint32_t bl1 = Flo[sB + cb];
            MMA_BF16(acc[nt], ah0, ah1, ah2, ah3, bh0, bh1);
            MMA_BF16(acc[nt], al0, al1, al2, al3, bh0, bh1);
            MMA_BF16(acc[nt], ah0, ah1, ah2, ah3, bl0, bl1);
        }
    }

    // ---- phase 3: den quad-reduction + epilogue ----
    den0 += __shfl_xor_sync(0xffffffffu, den0, 1);
    den0 += __shfl_xor_sync(0xffffffffu, den0, 2);
    den1 += __shfl_xor_sync(0xffffffffu, den1, 1);
    den1 += __shfl_xor_sync(0xffffffffu, den1, 2);
    const float inv0 = 1.0f / fmaxf(den0, 1e-8f);
    const float inv1 = 1.0f / fmaxf(den1, 1e-8f);

    float* obase = out + (size_t)y * WH + x0;
#pragma unroll
    for (int nt = 0; nt < 16; nt++) {
        const int ch = nt * 8 + lr * 2;
        float* o = obase + (size_t)ch * HW;
        o[0]      = acc[nt][0] * inv0;
        o[HW]     = acc[nt][1] * inv0;
        o[8]      = acc[nt][2] * inv1;
        o[HW + 8] = acc[nt][3] * inv1;
    }
}

extern "C" void kernel_launch(void* const* d_in, const int* in_sizes, int n_in,
                              void* d_out, int out_size) {
    const float* feat  = (const float*)d_in[0];
    const float* guide = (const float*)d_in[1];
    const float* sx    = (const float*)d_in[2];
    const float* sy    = (const float*)d_in[3];
    const float* th    = (const float*)d_in[4];
    const float* sr    = (const float*)d_in[5];
    float* out = (float*)d_out;

    cudaFuncSetAttribute(jbu_main_kernel,
                         cudaFuncAttributeMaxDynamicSharedMemorySize, SMEM_BYTES);

    jbu_prep_kernel<<<512, 256>>>(feat, guide);
    dim3 grid(WL, HL, 2);
    jbu_main_kernel<<<grid, 256, SMEM_BYTES>>>(guide, sx, sy, th, sr, out);
}